// round 3
// baseline (speedup 1.0000x reference)
#include <cuda_runtime.h>
#include <cuda_fp16.h>
#include <cstdint>

// ============================================================================
// Static device scratch (no dynamic allocation allowed)
// ============================================================================
__device__ __half g_xh[8192ull * 4096];  // x  in fp16 (64 MB)
__device__ __half g_wh[4096ull * 4096];  // dequantized W in fp16 (32 MB)
__device__ __half g_th[8192ull * 64];    // t = x @ (2*lora_A)^T in fp16
__device__ __half g_ah[64ull * 4096];    // 2*lora_A fp16
__device__ __half g_bh[4096ull * 64];    // lora_B fp16

__constant__ float NF4C[16] = {
    -1.0f, -0.6961928009986877f, -0.5250730514526367f, -0.39491748809814453f,
    -0.28444138169288635f, -0.18477343022823334f, -0.09105003625154495f, 0.0f,
    0.07958029955625534f, 0.16093020141124725f, 0.24611230194568634f, 0.33791524171829224f,
    0.44070982933044434f, 0.5626170039176941f, 0.7229568362236023f, 1.0f };

// ============================================================================
// Helpers (base sm_103 target: cp.async + ldmatrix + mma.sync only)
// ============================================================================
__device__ __forceinline__ uint32_t smem_to_u32(const void* p) {
    uint32_t a;
    asm("{ .reg .u64 t; cvta.to.shared.u64 t, %1; cvt.u32.u64 %0, t; }" : "=r"(a) : "l"(p));
    return a;
}
__device__ __forceinline__ void cp_async16(uint32_t s, const void* g) {
    asm volatile("cp.async.cg.shared.global [%0], [%1], 16;" :: "r"(s), "l"(g));
}
#define CP_COMMIT() asm volatile("cp.async.commit_group;" ::: "memory")
template <int N>
__device__ __forceinline__ void cp_wait_group() {
    asm volatile("cp.async.wait_group %0;" :: "n"(N) : "memory");
}
__device__ __forceinline__ void ldsm_x4(uint32_t* r, uint32_t addr) {
    asm volatile("ldmatrix.sync.aligned.m8n8.x4.shared.b16 {%0,%1,%2,%3}, [%4];"
                 : "=r"(r[0]), "=r"(r[1]), "=r"(r[2]), "=r"(r[3]) : "r"(addr));
}
__device__ __forceinline__ void mma16816(float* d, const uint32_t* a, const uint32_t* b) {
    asm volatile("mma.sync.aligned.m16n8k16.row.col.f32.f16.f16.f32 "
                 "{%0,%1,%2,%3}, {%4,%5,%6,%7}, {%8,%9}, {%0,%1,%2,%3};"
                 : "+f"(d[0]), "+f"(d[1]), "+f"(d[2]), "+f"(d[3])
                 : "r"(a[0]), "r"(a[1]), "r"(a[2]), "r"(a[3]), "r"(b[0]), "r"(b[1]));
}

// ============================================================================
// Prep kernels
// ============================================================================
__global__ void conv_x_kernel(const float* __restrict__ x) {
    const int N4 = 8192 * 4096 / 4;
    for (int i = blockIdx.x * blockDim.x + threadIdx.x; i < N4; i += gridDim.x * blockDim.x) {
        float4 v = reinterpret_cast<const float4*>(x)[i];
        __half2 h0 = __floats2half2_rn(v.x, v.y);
        __half2 h1 = __floats2half2_rn(v.z, v.w);
        reinterpret_cast<__half2*>(g_xh)[2 * i + 0] = h0;
        reinterpret_cast<__half2*>(g_xh)[2 * i + 1] = h1;
    }
}

__global__ void deq_w_kernel(const int* __restrict__ codes, const float* __restrict__ absmax) {
    __shared__ float tab[16];
    if (threadIdx.x < 16) tab[threadIdx.x] = NF4C[threadIdx.x];
    __syncthreads();
    const int N4 = 4096 * 4096 / 4;
    for (int i = blockIdx.x * blockDim.x + threadIdx.x; i < N4; i += gridDim.x * blockDim.x) {
        int4 c = reinterpret_cast<const int4*>(codes)[i];
        float am = absmax[i >> 4];  // 4 elems per i, 64 per block -> block = i/16
        __half2 h0 = __floats2half2_rn(tab[c.x & 15] * am, tab[c.y & 15] * am);
        __half2 h1 = __floats2half2_rn(tab[c.z & 15] * am, tab[c.w & 15] * am);
        reinterpret_cast<__half2*>(g_wh)[2 * i + 0] = h0;
        reinterpret_cast<__half2*>(g_wh)[2 * i + 1] = h1;
    }
}

__global__ void conv_ab_kernel(const float* __restrict__ la, const float* __restrict__ lb) {
    const int N = 64 * 4096;
    for (int i = blockIdx.x * blockDim.x + threadIdx.x; i < N; i += gridDim.x * blockDim.x) {
        g_ah[i] = __float2half_rn(2.0f * la[i]);  // SCALING folded into A
        g_bh[i] = __float2half_rn(lb[i]);
    }
}

// ============================================================================
// fp16 GEMM, fp32 accumulate:  out[BM,BN] tile = A[m0:,K] @ B[n0:,K]^T
//   - BK = 32 halfs (64B/row), rows padded to 80B -> conflict-free ldmatrix
//   - NST-stage cp.async pipeline
//   - AUG: 2 extra K-slabs from (A2 ld=64, B2 ld=64)  [LoRA K-augmentation]
//   - OUTH: write fp16 (for the t pass) instead of fp32
// ============================================================================
template <int BM, int BN, int NST, bool AUG, bool OUTH>
__global__ void __launch_bounds__((BM / 64) * (BN / 32) * 32)
hgemm_kernel(const __half* __restrict__ Ag, const __half* __restrict__ Bg,
             const __half* __restrict__ A2, const __half* __restrict__ B2,
             void* __restrict__ outp, int ldo) {
    constexpr int NWN = BN / 32, NWM = BM / 64;
    constexpr int NTHR = NWM * NWN * 32;
    constexpr int ROWB = 80;                    // 64B data + 16B pad
    constexpr int ASTG = BM * ROWB, BSTG = BN * ROWB, STG = ASTG + BSTG;
    constexpr int BASE_IT = 128;                // K=4096 / BK=32
    constexpr int NIT = AUG ? BASE_IT + 2 : BASE_IT;

    extern __shared__ char smem[];
    const uint32_t sb = smem_to_u32(smem);
    const int tid = threadIdx.x, lid = tid & 31, wid = tid >> 5;
    const int wm = wid / NWN, wn = wid % NWN;
    const int m0 = blockIdx.y * BM, n0 = blockIdx.x * BN;

    auto issue = [&](int it) {
        const int stg = it % NST;
        const uint32_t abase = sb + stg * STG;
        const uint32_t bbase = abase + ASTG;
        const __half* Ap;
        const __half* Bp;
        int lda, ldb, kb;
        if (!AUG || it < BASE_IT) {
            Ap = Ag; Bp = Bg; lda = 4096; ldb = 4096; kb = it * 32;
        } else {
            Ap = A2; Bp = B2; lda = 64; ldb = 64; kb = (it - BASE_IT) * 32;
        }
        #pragma unroll
        for (int c = tid; c < BM * 4; c += NTHR) {
            int row = c >> 2, kc = c & 3;
            cp_async16(abase + row * ROWB + kc * 16,
                       Ap + (size_t)(m0 + row) * lda + kb + kc * 8);
        }
        #pragma unroll
        for (int c = tid; c < BN * 4; c += NTHR) {
            int row = c >> 2, kc = c & 3;
            cp_async16(bbase + row * ROWB + kc * 16,
                       Bp + (size_t)(n0 + row) * ldb + kb + kc * 8);
        }
    };

    for (int it = 0; it < NST - 1 && it < NIT; ++it) { issue(it); CP_COMMIT(); }

    float acc[4][4][4];
    #pragma unroll
    for (int i = 0; i < 4; i++)
        #pragma unroll
        for (int j = 0; j < 4; j++)
            #pragma unroll
            for (int k = 0; k < 4; k++) acc[i][j][k] = 0.0f;

    for (int it = 0; it < NIT; ++it) {
        cp_wait_group<NST - 2>();
        __syncthreads();
        if (it + NST - 1 < NIT) issue(it + NST - 1);
        CP_COMMIT();

        const int stg = it % NST;
        const uint32_t abase = sb + stg * STG + wm * 64 * ROWB;
        const uint32_t bbase = sb + stg * STG + ASTG + wn * 32 * ROWB;
        #pragma unroll
        for (int ks = 0; ks < 2; ++ks) {
            uint32_t a[4][4], b[2][4];
            #pragma unroll
            for (int mt = 0; mt < 4; ++mt) {
                uint32_t addr = abase +
                    (mt * 16 + (lid & 7) + ((lid >> 3) & 1) * 8) * ROWB +
                    ks * 32 + (lid >> 4) * 16;
                ldsm_x4(a[mt], addr);
            }
            #pragma unroll
            for (int p = 0; p < 2; ++p) {
                uint32_t addr = bbase +
                    (p * 16 + (lid & 7) + ((lid >> 4) & 1) * 8) * ROWB +
                    ks * 32 + ((lid >> 3) & 1) * 16;
                ldsm_x4(b[p], addr);
            }
            #pragma unroll
            for (int mt = 0; mt < 4; ++mt)
                #pragma unroll
                for (int nt = 0; nt < 4; ++nt) {
                    uint32_t bb[2] = { b[nt >> 1][(nt & 1) * 2],
                                       b[nt >> 1][(nt & 1) * 2 + 1] };
                    mma16816(acc[mt][nt], a[mt], bb);
                }
        }
    }

    // Epilogue
    #pragma unroll
    for (int mt = 0; mt < 4; ++mt) {
        #pragma unroll
        for (int nt = 0; nt < 4; ++nt) {
            int r  = m0 + wm * 64 + mt * 16 + (lid >> 2);
            int cn = n0 + wn * 32 + nt * 8 + 2 * (lid & 3);
            float* ac = acc[mt][nt];
            if (!OUTH) {
                float* out = (float*)outp;
                *reinterpret_cast<float2*>(out + (size_t)r * ldo + cn) =
                    make_float2(ac[0], ac[1]);
                *reinterpret_cast<float2*>(out + (size_t)(r + 8) * ldo + cn) =
                    make_float2(ac[2], ac[3]);
            } else {
                __half* out = (__half*)outp;
                *reinterpret_cast<__half2*>(out + (size_t)r * ldo + cn) =
                    __floats2half2_rn(ac[0], ac[1]);
                *reinterpret_cast<__half2*>(out + (size_t)(r + 8) * ldo + cn) =
                    __floats2half2_rn(ac[2], ac[3]);
            }
        }
    }
}

// ============================================================================
// Host side
// ============================================================================
extern "C" void kernel_launch(void* const* d_in, const int* in_sizes, int n_in,
                              void* d_out, int out_size) {
    const float* x      = (const float*)d_in[0];  // [4,2048,4096] -> [8192,4096]
    const float* lora_A = (const float*)d_in[1];  // [64,4096]
    const float* lora_B = (const float*)d_in[2];  // [4096,64]
    const float* absmax = (const float*)d_in[3];  // [262144]
    const int*   codes  = (const int*)d_in[4];    // [4096,4096]
    float* out = (float*)d_out;

    void *xh, *wh, *th, *ah, *bh;
    cudaGetSymbolAddress(&xh, g_xh);
    cudaGetSymbolAddress(&wh, g_wh);
    cudaGetSymbolAddress(&th, g_th);
    cudaGetSymbolAddress(&ah, g_ah);
    cudaGetSymbolAddress(&bh, g_bh);

    conv_x_kernel<<<2048, 256>>>(x);
    deq_w_kernel<<<2048, 256>>>(codes, absmax);
    conv_ab_kernel<<<512, 256>>>(lora_A, lora_B);

    // t = x @ (2*lora_A)^T : M=8192, N=64, K=4096 ; fp16 output
    {
        constexpr int SM = (128 * 80 + 64 * 80) * 4;  // 61440
        auto k = hgemm_kernel<128, 64, 4, false, true>;
        cudaFuncSetAttribute((const void*)k, cudaFuncAttributeMaxDynamicSharedMemorySize, SM);
        k<<<dim3(1, 64), 128, SM>>>((const __half*)xh, (const __half*)ah,
                                    (const __half*)xh, (const __half*)ah, th, 64);
    }
    // out = x @ W^T + t @ lora_B^T (K-augmented): M=8192, N=4096, K=4096+64
    {
        constexpr int SM = (128 * 80 + 128 * 80) * 4;  // 81920
        auto k = hgemm_kernel<128, 128, 4, true, false>;
        cudaFuncSetAttribute((const void*)k, cudaFuncAttributeMaxDynamicSharedMemorySize, SM);
        k<<<dim3(32, 64), 256, SM>>>((const __half*)xh, (const __half*)wh,
                                     (const __half*)th, (const __half*)bh, out, 4096);
    }
}

// round 4
// speedup vs baseline: 1.3492x; 1.3492x over previous
#include <cuda_runtime.h>
#include <cuda_fp16.h>
#include <cstdint>

// ============================================================================
// Static device scratch (no dynamic allocation allowed)
// ============================================================================
__device__ __half g_xh[8192ull * 4096];  // x  in fp16 (64 MB)
__device__ __half g_wh[4096ull * 4096];  // dequantized W in fp16 (32 MB)
__device__ __half g_th[8192ull * 64];    // t = x @ (2*lora_A)^T in fp16
__device__ __half g_ah[64ull * 4096];    // 2*lora_A fp16
__device__ __half g_bh[4096ull * 64];    // lora_B fp16

__constant__ float NF4C[16] = {
    -1.0f, -0.6961928009986877f, -0.5250730514526367f, -0.39491748809814453f,
    -0.28444138169288635f, -0.18477343022823334f, -0.09105003625154495f, 0.0f,
    0.07958029955625534f, 0.16093020141124725f, 0.24611230194568634f, 0.33791524171829224f,
    0.44070982933044434f, 0.5626170039176941f, 0.7229568362236023f, 1.0f };

// ============================================================================
// Helpers (base sm_103 target: cp.async + ldmatrix + mma.sync only)
// ============================================================================
__device__ __forceinline__ uint32_t smem_to_u32(const void* p) {
    uint32_t a;
    asm("{ .reg .u64 t; cvta.to.shared.u64 t, %1; cvt.u32.u64 %0, t; }" : "=r"(a) : "l"(p));
    return a;
}
__device__ __forceinline__ void cp_async16(uint32_t s, const void* g) {
    asm volatile("cp.async.cg.shared.global [%0], [%1], 16;" :: "r"(s), "l"(g));
}
#define CP_COMMIT() asm volatile("cp.async.commit_group;" ::: "memory")
template <int N>
__device__ __forceinline__ void cp_wait_group() {
    asm volatile("cp.async.wait_group %0;" :: "n"(N) : "memory");
}
__device__ __forceinline__ void ldsm_x4(uint32_t* r, uint32_t addr) {
    asm volatile("ldmatrix.sync.aligned.m8n8.x4.shared.b16 {%0,%1,%2,%3}, [%4];"
                 : "=r"(r[0]), "=r"(r[1]), "=r"(r[2]), "=r"(r[3]) : "r"(addr));
}
__device__ __forceinline__ void mma16816(float* d, const uint32_t* a, const uint32_t* b) {
    asm volatile("mma.sync.aligned.m16n8k16.row.col.f32.f16.f16.f32 "
                 "{%0,%1,%2,%3}, {%4,%5,%6,%7}, {%8,%9}, {%0,%1,%2,%3};"
                 : "+f"(d[0]), "+f"(d[1]), "+f"(d[2]), "+f"(d[3])
                 : "r"(a[0]), "r"(a[1]), "r"(a[2]), "r"(a[3]), "r"(b[0]), "r"(b[1]));
}

// ============================================================================
// Prep kernels
// ============================================================================
__global__ void conv_x_kernel(const float* __restrict__ x) {
    const int N4 = 8192 * 4096 / 4;
    for (int i = blockIdx.x * blockDim.x + threadIdx.x; i < N4; i += gridDim.x * blockDim.x) {
        float4 v = reinterpret_cast<const float4*>(x)[i];
        __half2 h0 = __floats2half2_rn(v.x, v.y);
        __half2 h1 = __floats2half2_rn(v.z, v.w);
        reinterpret_cast<__half2*>(g_xh)[2 * i + 0] = h0;
        reinterpret_cast<__half2*>(g_xh)[2 * i + 1] = h1;
    }
}

__global__ void deq_w_kernel(const int* __restrict__ codes, const float* __restrict__ absmax) {
    __shared__ float tab[16];
    if (threadIdx.x < 16) tab[threadIdx.x] = NF4C[threadIdx.x];
    __syncthreads();
    const int N4 = 4096 * 4096 / 4;
    for (int i = blockIdx.x * blockDim.x + threadIdx.x; i < N4; i += gridDim.x * blockDim.x) {
        int4 c = reinterpret_cast<const int4*>(codes)[i];
        float am = absmax[i >> 4];  // 4 elems per i, 64 per block -> block = i/16
        __half2 h0 = __floats2half2_rn(tab[c.x & 15] * am, tab[c.y & 15] * am);
        __half2 h1 = __floats2half2_rn(tab[c.z & 15] * am, tab[c.w & 15] * am);
        reinterpret_cast<__half2*>(g_wh)[2 * i + 0] = h0;
        reinterpret_cast<__half2*>(g_wh)[2 * i + 1] = h1;
    }
}

__global__ void conv_ab_kernel(const float* __restrict__ la, const float* __restrict__ lb) {
    const int N = 64 * 4096;
    for (int i = blockIdx.x * blockDim.x + threadIdx.x; i < N; i += gridDim.x * blockDim.x) {
        g_ah[i] = __float2half_rn(2.0f * la[i]);  // SCALING folded into A
        g_bh[i] = __float2half_rn(lb[i]);
    }
}

// ============================================================================
// fp16 GEMM, fp32 accumulate:  out[BM,BN] tile = A[m0:,K] @ B[n0:,K]^T
//   - warp tile 64 x WN ; BK = 32 halfs (64B/row), rows padded to 80B
//   - NST-stage cp.async pipeline, 2 CTAs/SM
//   - AUG: 2 extra K-slabs from (A2 ld=64, B2 ld=64)  [LoRA K-augmentation]
//   - OUTH: write fp16 (for the t pass) instead of fp32
// ============================================================================
template <int BM, int BN, int WN, int NST, bool AUG, bool OUTH>
__global__ void __launch_bounds__((BM / 64) * (BN / WN) * 32, 2)
hgemm_kernel(const __half* __restrict__ Ag, const __half* __restrict__ Bg,
             const __half* __restrict__ A2, const __half* __restrict__ B2,
             void* __restrict__ outp, int ldo) {
    constexpr int NWN = BN / WN, NWM = BM / 64;
    constexpr int NTHR = NWM * NWN * 32;
    constexpr int NT = WN / 8;                  // n-tiles per warp
    constexpr int NP = WN / 16;                 // ldsm b-groups per warp
    constexpr int ROWB = 80;                    // 64B data + 16B pad
    constexpr int ASTG = BM * ROWB, BSTG = BN * ROWB, STG = ASTG + BSTG;
    constexpr int BASE_IT = 128;                // K=4096 / BK=32
    constexpr int NIT = AUG ? BASE_IT + 2 : BASE_IT;

    extern __shared__ char smem[];
    const uint32_t sb = smem_to_u32(smem);
    const int tid = threadIdx.x, lid = tid & 31, wid = tid >> 5;
    const int wm = wid / NWN, wn = wid % NWN;
    const int m0 = blockIdx.y * BM, n0 = blockIdx.x * BN;

    auto issue = [&](int it) {
        const int stg = it % NST;
        const uint32_t abase = sb + stg * STG;
        const uint32_t bbase = abase + ASTG;
        const __half* Ap;
        const __half* Bp;
        int lda, ldb, kb;
        if (!AUG || it < BASE_IT) {
            Ap = Ag; Bp = Bg; lda = 4096; ldb = 4096; kb = it * 32;
        } else {
            Ap = A2; Bp = B2; lda = 64; ldb = 64; kb = (it - BASE_IT) * 32;
        }
        #pragma unroll
        for (int c = tid; c < BM * 4; c += NTHR) {
            int row = c >> 2, kc = c & 3;
            cp_async16(abase + row * ROWB + kc * 16,
                       Ap + (size_t)(m0 + row) * lda + kb + kc * 8);
        }
        #pragma unroll
        for (int c = tid; c < BN * 4; c += NTHR) {
            int row = c >> 2, kc = c & 3;
            cp_async16(bbase + row * ROWB + kc * 16,
                       Bp + (size_t)(n0 + row) * ldb + kb + kc * 8);
        }
    };

    for (int it = 0; it < NST - 1 && it < NIT; ++it) { issue(it); CP_COMMIT(); }

    float acc[4][NT][4];
    #pragma unroll
    for (int i = 0; i < 4; i++)
        #pragma unroll
        for (int j = 0; j < NT; j++)
            #pragma unroll
            for (int k = 0; k < 4; k++) acc[i][j][k] = 0.0f;

    for (int it = 0; it < NIT; ++it) {
        cp_wait_group<NST - 2>();
        __syncthreads();
        if (it + NST - 1 < NIT) issue(it + NST - 1);
        CP_COMMIT();

        const int stg = it % NST;
        const uint32_t abase = sb + stg * STG + wm * 64 * ROWB;
        const uint32_t bbase = sb + stg * STG + ASTG + wn * WN * ROWB;
        #pragma unroll
        for (int ks = 0; ks < 2; ++ks) {
            uint32_t a[4][4], b[NP][4];
            #pragma unroll
            for (int mt = 0; mt < 4; ++mt) {
                uint32_t addr = abase +
                    (mt * 16 + (lid & 7) + ((lid >> 3) & 1) * 8) * ROWB +
                    ks * 32 + (lid >> 4) * 16;
                ldsm_x4(a[mt], addr);
            }
            #pragma unroll
            for (int p = 0; p < NP; ++p) {
                uint32_t addr = bbase +
                    (p * 16 + (lid & 7) + ((lid >> 4) & 1) * 8) * ROWB +
                    ks * 32 + ((lid >> 3) & 1) * 16;
                ldsm_x4(b[p], addr);
            }
            #pragma unroll
            for (int mt = 0; mt < 4; ++mt)
                #pragma unroll
                for (int nt = 0; nt < NT; ++nt) {
                    uint32_t bb[2] = { b[nt >> 1][(nt & 1) * 2],
                                       b[nt >> 1][(nt & 1) * 2 + 1] };
                    mma16816(acc[mt][nt], a[mt], bb);
                }
        }
    }

    // Epilogue
    #pragma unroll
    for (int mt = 0; mt < 4; ++mt) {
        #pragma unroll
        for (int nt = 0; nt < NT; ++nt) {
            int r  = m0 + wm * 64 + mt * 16 + (lid >> 2);
            int cn = n0 + wn * WN + nt * 8 + 2 * (lid & 3);
            float* ac = acc[mt][nt];
            if (!OUTH) {
                float* out = (float*)outp;
                *reinterpret_cast<float2*>(out + (size_t)r * ldo + cn) =
                    make_float2(ac[0], ac[1]);
                *reinterpret_cast<float2*>(out + (size_t)(r + 8) * ldo + cn) =
                    make_float2(ac[2], ac[3]);
            } else {
                __half* out = (__half*)outp;
                *reinterpret_cast<__half2*>(out + (size_t)r * ldo + cn) =
                    __floats2half2_rn(ac[0], ac[1]);
                *reinterpret_cast<__half2*>(out + (size_t)(r + 8) * ldo + cn) =
                    __floats2half2_rn(ac[2], ac[3]);
            }
        }
    }
}

// ============================================================================
// Host side
// ============================================================================
extern "C" void kernel_launch(void* const* d_in, const int* in_sizes, int n_in,
                              void* d_out, int out_size) {
    const float* x      = (const float*)d_in[0];  // [4,2048,4096] -> [8192,4096]
    const float* lora_A = (const float*)d_in[1];  // [64,4096]
    const float* lora_B = (const float*)d_in[2];  // [4096,64]
    const float* absmax = (const float*)d_in[3];  // [262144]
    const int*   codes  = (const int*)d_in[4];    // [4096,4096]
    float* out = (float*)d_out;

    void *xh, *wh, *th, *ah, *bh;
    cudaGetSymbolAddress(&xh, g_xh);
    cudaGetSymbolAddress(&wh, g_wh);
    cudaGetSymbolAddress(&th, g_th);
    cudaGetSymbolAddress(&ah, g_ah);
    cudaGetSymbolAddress(&bh, g_bh);

    conv_x_kernel<<<2048, 256>>>(x);
    deq_w_kernel<<<2048, 256>>>(codes, absmax);
    conv_ab_kernel<<<512, 256>>>(lora_A, lora_B);

    // t = x @ (2*lora_A)^T : M=8192, N=64, K=4096 ; fp16 output
    {
        constexpr int SM = (64 * 80 + 64 * 80) * 4;  // 40960
        auto k = hgemm_kernel<64, 64, 32, 4, false, true>;
        cudaFuncSetAttribute((const void*)k, cudaFuncAttributeMaxDynamicSharedMemorySize, SM);
        k<<<dim3(1, 128), 64, SM>>>((const __half*)xh, (const __half*)ah,
                                    (const __half*)xh, (const __half*)ah, th, 64);
    }
    // out = x @ W^T + t @ lora_B^T (K-augmented): M=8192, N=4096, K=4096+64
    {
        constexpr int SM = (128 * 80 + 128 * 80) * 4;  // 81920
        auto k = hgemm_kernel<128, 128, 64, 4, true, false>;
        cudaFuncSetAttribute((const void*)k, cudaFuncAttributeMaxDynamicSharedMemorySize, SM);
        k<<<dim3(32, 64), 128, SM>>>((const __half*)xh, (const __half*)wh,
                                     (const __half*)th, (const __half*)bh, out, 4096);
    }
}